// round 7
// baseline (speedup 1.0000x reference)
#include <cuda_runtime.h>

#define M_SLOTS 16
#define KEY_DIM 1024
#define TPB     256

// Cross-block handshake state. Zero-initialized at module load; the LAST
// block of every launch resets it, so every graph replay starts clean.
__device__ float        g_wbuf[M_SLOTS];
__device__ unsigned int g_flag;   // 0 = weights not ready, 1 = ready
__device__ unsigned int g_done;   // completion counter for reset

// ---------------------------------------------------------------------------
// Single fused kernel.
//  block 0   : computes cosine-sim + softmax (68KB read once), publishes
//              weights with a release store, then does its own tile.
//  blocks >0 : prefetch their 16 V lines into L2 (asm volatile -> cannot be
//              sunk), spin on acquire flag, then stream.
// ---------------------------------------------------------------------------
__global__ void __launch_bounds__(TPB, 6) fused_kernel(
        const float*  __restrict__ task_emb,
        const float*  __restrict__ K_memory,
        const float4* __restrict__ V0,
        const float4* __restrict__ V1,
        float4*       __restrict__ out,
        int nv4_0, int nv4_1) {
    __shared__ float s_w[M_SLOTS];
    __shared__ float s_cos[M_SLOTS];

    const int tid = threadIdx.x;

    // ---- tile addressing (needed early for prefetch) ----
    const int i = blockIdx.x * TPB + tid;         // grid is an exact fit
    const float4* __restrict__ V;
    size_t stride;
    int idx;
    if (i < nv4_0) { V = V0; idx = i;          stride = (size_t)nv4_0; }
    else           { V = V1; idx = i - nv4_0;  stride = (size_t)nv4_1; }

    if (blockIdx.x == 0) {
        // ---------------- Phase A: weights (block 0 only) ----------------
        const int warp = tid >> 5;       // 0..7, 2 slots each
        const int lane = tid & 31;
        const int sa = 2 * warp, sb = 2 * warp + 1;
        const float4* t4 = (const float4*)task_emb;
        const float4* ka = (const float4*)(K_memory + sa * KEY_DIM);
        const float4* kb = (const float4*)(K_memory + sb * KEY_DIM);

        float dota = 0.f, dotb = 0.f, kka = 0.f, kkb = 0.f, tt = 0.f;
        #pragma unroll
        for (int j = 0; j < 8; j++) {
            float4 t = t4[lane + 32 * j];
            float4 a = ka[lane + 32 * j];
            float4 b = kb[lane + 32 * j];
            dota = fmaf(t.x, a.x, dota); dota = fmaf(t.y, a.y, dota);
            dota = fmaf(t.z, a.z, dota); dota = fmaf(t.w, a.w, dota);
            dotb = fmaf(t.x, b.x, dotb); dotb = fmaf(t.y, b.y, dotb);
            dotb = fmaf(t.z, b.z, dotb); dotb = fmaf(t.w, b.w, dotb);
            kka  = fmaf(a.x, a.x, kka);  kka  = fmaf(a.y, a.y, kka);
            kka  = fmaf(a.z, a.z, kka);  kka  = fmaf(a.w, a.w, kka);
            kkb  = fmaf(b.x, b.x, kkb);  kkb  = fmaf(b.y, b.y, kkb);
            kkb  = fmaf(b.z, b.z, kkb);  kkb  = fmaf(b.w, b.w, kkb);
            tt   = fmaf(t.x, t.x, tt);   tt   = fmaf(t.y, t.y, tt);
            tt   = fmaf(t.z, t.z, tt);   tt   = fmaf(t.w, t.w, tt);
        }
        #pragma unroll
        for (int off = 16; off > 0; off >>= 1) {
            dota += __shfl_down_sync(0xffffffffu, dota, off);
            dotb += __shfl_down_sync(0xffffffffu, dotb, off);
            kka  += __shfl_down_sync(0xffffffffu, kka,  off);
            kkb  += __shfl_down_sync(0xffffffffu, kkb,  off);
            tt   += __shfl_down_sync(0xffffffffu, tt,   off);
        }
        if (lane == 0) {
            float n1 = sqrtf(tt);
            s_cos[sa] = dota / fmaxf(n1 * sqrtf(kka), 1e-6f);
            s_cos[sb] = dotb / fmaxf(n1 * sqrtf(kkb), 1e-6f);
        }
        __syncthreads();

        if (tid == 0) {
            float c[M_SLOTS];
            float mx = -1e30f;
            #pragma unroll
            for (int m = 0; m < M_SLOTS; m++) { c[m] = s_cos[m]; mx = fmaxf(mx, c[m]); }
            float sum = 0.f;
            #pragma unroll
            for (int m = 0; m < M_SLOTS; m++) { c[m] = __expf(c[m] - mx); sum += c[m]; }
            float inv = 1.0f / sum;
            #pragma unroll
            for (int m = 0; m < M_SLOTS; m++) {
                float wm = c[m] * inv;
                s_w[m]    = wm;
                g_wbuf[m] = wm;
            }
            __threadfence();
            unsigned int* fp = &g_flag;
            asm volatile("st.release.gpu.u32 [%0], %1;" :: "l"(fp), "r"(1u) : "memory");
        }
        __syncthreads();
    } else {
        // ---------------- other blocks: prefetch, then wait ----------------
        unsigned int f0;
        unsigned int* fp = &g_flag;
        asm volatile("ld.relaxed.gpu.u32 %0, [%1];" : "=r"(f0) : "l"(fp) : "memory");
        if (f0 == 0) {
            // Weights not ready yet: pull this tile's 16 lines toward L2 now.
            #pragma unroll
            for (int m = 0; m < M_SLOTS; m++) {
                const float4* p = V + (size_t)m * stride + (size_t)idx;
                asm volatile("prefetch.global.L2 [%0];" :: "l"(p));
            }
        }
        if (tid == 0) {
            unsigned int f;
            do {
                asm volatile("ld.acquire.gpu.u32 %0, [%1];" : "=r"(f) : "l"(fp) : "memory");
                if (f) break;
                __nanosleep(64);
            } while (true);
        }
        __syncthreads();               // orders tid0's acquire with the reads below
        if (tid < M_SLOTS) s_w[tid] = g_wbuf[tid];
        __syncthreads();
    }

    // ---------------- Phase B: streaming weighted sum ----------------
    float4 acc = make_float4(0.f, 0.f, 0.f, 0.f);
    #pragma unroll
    for (int m = 0; m < M_SLOTS; m++) {
        float4 v = V[(size_t)m * stride + (size_t)idx];
        float wm = s_w[m];
        acc.x = fmaf(wm, v.x, acc.x);
        acc.y = fmaf(wm, v.y, acc.y);
        acc.z = fmaf(wm, v.z, acc.z);
        acc.w = fmaf(wm, v.w, acc.w);
    }
    out[i] = acc;

    // ---------------- reset handshake for the next graph replay ----------------
    __syncthreads();
    if (tid == 0) {
        unsigned int d = atomicAdd(&g_done, 1u);
        if (d == gridDim.x - 1) {      // last block: everyone passed the spin
            g_done = 0;
            g_flag = 0;
        }
    }
}

// ---------------------------------------------------------------------------
// Launch contract
// Inputs (metadata order): task_emb [1,1024] f32, K_memory [16,1024] f32,
//                          V0 [16,1024,1024] f32, V1 [16,1024,4096] f32
// Output: rec0 [1024,1024] f32 followed by rec1 [1024,4096] f32
// ---------------------------------------------------------------------------
extern "C" void kernel_launch(void* const* d_in, const int* in_sizes, int n_in,
                              void* d_out, int out_size) {
    const float* task_emb = (const float*)d_in[0];
    const float* K_memory = (const float*)d_in[1];
    const float* V0       = (const float*)d_in[2];
    const float* V1       = (const float*)d_in[3];
    float* out = (float*)d_out;

    const int n0 = in_sizes[2] / M_SLOTS;   // 1024*1024
    const int n1 = in_sizes[3] / M_SLOTS;   // 1024*4096
    const int nv4_0 = n0 / 4;               // 262144
    const int nv4_1 = n1 / 4;               // 1048576
    const int total = nv4_0 + nv4_1;        // 1310720 = 5120 * 256 exactly

    fused_kernel<<<total / TPB, TPB>>>(task_emb, K_memory,
                                       (const float4*)V0, (const float4*)V1,
                                       (float4*)out, nv4_0, nv4_1);
}

// round 8
// speedup vs baseline: 1.0809x; 1.0809x over previous
#include <cuda_runtime.h>

#define M_SLOTS 16
#define KEY_DIM 1024
#define TPB     256

// softmax weights, produced by weights_kernel, consumed by wsum_fused_kernel
__device__ float g_w[M_SLOTS];

// ---------------------------------------------------------------------------
// Kernel 1 (PDL primary): cosine similarity + softmax over 16 memory slots.
// Fires the programmatic launch trigger IMMEDIATELY so the secondary grid
// becomes resident and issues its V-loads while this kernel runs.
// ---------------------------------------------------------------------------
__global__ void __launch_bounds__(512) weights_kernel(
        const float* __restrict__ task_emb,
        const float* __restrict__ K_memory) {
#if __CUDA_ARCH__ >= 900
    cudaTriggerProgrammaticLaunchCompletion();
#endif
    __shared__ float s_cos[M_SLOTS];
    const int warp = threadIdx.x >> 5;
    const int lane = threadIdx.x & 31;

    const float4* t4 = (const float4*)task_emb;                 // 256 float4
    const float4* k4 = (const float4*)(K_memory + warp * KEY_DIM);

    float dot = 0.f, kk = 0.f, tt = 0.f;
    #pragma unroll
    for (int j = 0; j < 8; j++) {
        float4 t  = t4[lane + 32 * j];
        float4 km = k4[lane + 32 * j];
        dot = fmaf(t.x, km.x, dot); dot = fmaf(t.y, km.y, dot);
        dot = fmaf(t.z, km.z, dot); dot = fmaf(t.w, km.w, dot);
        kk  = fmaf(km.x, km.x, kk); kk  = fmaf(km.y, km.y, kk);
        kk  = fmaf(km.z, km.z, kk); kk  = fmaf(km.w, km.w, kk);
        tt  = fmaf(t.x,  t.x,  tt); tt  = fmaf(t.y,  t.y,  tt);
        tt  = fmaf(t.z,  t.z,  tt); tt  = fmaf(t.w,  t.w,  tt);
    }
    #pragma unroll
    for (int off = 16; off > 0; off >>= 1) {
        dot += __shfl_down_sync(0xffffffffu, dot, off);
        kk  += __shfl_down_sync(0xffffffffu, kk,  off);
        tt  += __shfl_down_sync(0xffffffffu, tt,  off);
    }
    if (lane == 0) {
        float denom = fmaxf(sqrtf(tt) * sqrtf(kk), 1e-6f);
        s_cos[warp] = dot / denom;
    }
    __syncthreads();

    if (threadIdx.x == 0) {
        float mx = -1e30f;
        #pragma unroll
        for (int m = 0; m < M_SLOTS; m++) mx = fmaxf(mx, s_cos[m]);
        float e[M_SLOTS];
        float sum = 0.f;
        #pragma unroll
        for (int m = 0; m < M_SLOTS; m++) {
            e[m] = __expf(s_cos[m] - mx);
            sum += e[m];
        }
        float inv = 1.0f / sum;
        #pragma unroll
        for (int m = 0; m < M_SLOTS; m++) g_w[m] = e[m] * inv;
    }
}

// ---------------------------------------------------------------------------
// Kernel 2 (PDL secondary): one grid covers both V0 and V1 segments.
// The 16 V-loads are issued as VOLATILE SASS loads (ld.global.nc.v4.f32) so
// ptxas cannot sink them below cudaGridDependencySynchronize() — in R5 a
// C-level memory clobber failed (regs stayed 32, loads were sunk). The 64
// live result registers are the proof signature (expect regs ~88).
// ---------------------------------------------------------------------------
__global__ void __launch_bounds__(TPB) wsum_fused_kernel(
        const float4* __restrict__ V0,
        const float4* __restrict__ V1,
        float4* __restrict__ out,
        int nv4_0, int nv4_1) {
    const int i = blockIdx.x * TPB + threadIdx.x;   // grid is an exact fit

    const float4* __restrict__ V;
    size_t stride;
    int idx;
    if (i < nv4_0) { V = V0; idx = i;          stride = (size_t)nv4_0; }
    else           { V = V1; idx = i - nv4_0;  stride = (size_t)nv4_1; }

    // Issue all 16 independent 128-bit loads NOW (before the PDL sync).
    float4 v[M_SLOTS];
#if __CUDA_ARCH__ >= 900
    #pragma unroll
    for (int m = 0; m < M_SLOTS; m++) {
        const float4* p = V + (size_t)m * stride + (size_t)idx;
        asm volatile("ld.global.nc.v4.f32 {%0, %1, %2, %3}, [%4];"
                     : "=f"(v[m].x), "=f"(v[m].y), "=f"(v[m].z), "=f"(v[m].w)
                     : "l"(p));
    }
    // Wait for weights_kernel completion (g_w visible) only now.
    cudaGridDependencySynchronize();
#else
    #pragma unroll
    for (int m = 0; m < M_SLOTS; m++)
        v[m] = V[(size_t)m * stride + (size_t)idx];
#endif

    float4 acc = make_float4(0.f, 0.f, 0.f, 0.f);
    #pragma unroll
    for (int m = 0; m < M_SLOTS; m++) {
        float wm = g_w[m];
        acc.x = fmaf(wm, v[m].x, acc.x);
        acc.y = fmaf(wm, v[m].y, acc.y);
        acc.z = fmaf(wm, v[m].z, acc.z);
        acc.w = fmaf(wm, v[m].w, acc.w);
    }
    out[i] = acc;
}

// ---------------------------------------------------------------------------
// Launch contract
// Inputs (metadata order): task_emb [1,1024] f32, K_memory [16,1024] f32,
//                          V0 [16,1024,1024] f32, V1 [16,1024,4096] f32
// Output: rec0 [1024,1024] f32 followed by rec1 [1024,4096] f32
// ---------------------------------------------------------------------------
extern "C" void kernel_launch(void* const* d_in, const int* in_sizes, int n_in,
                              void* d_out, int out_size) {
    const float* task_emb = (const float*)d_in[0];
    const float* K_memory = (const float*)d_in[1];
    const float* V0       = (const float*)d_in[2];
    const float* V1       = (const float*)d_in[3];
    float* out = (float*)d_out;

    const int n0 = in_sizes[2] / M_SLOTS;   // 1024*1024
    const int n1 = in_sizes[3] / M_SLOTS;   // 1024*4096
    const int nv4_0 = n0 / 4;               // 262144
    const int nv4_1 = n1 / 4;               // 1048576
    const int total = nv4_0 + nv4_1;        // 1310720 = 5120 * 256 exactly

    weights_kernel<<<1, 512>>>(task_emb, K_memory);

    // Secondary launch with programmatic stream serialization (PDL).
    cudaLaunchConfig_t cfg = {};
    cfg.gridDim  = dim3((unsigned)(total / TPB));
    cfg.blockDim = dim3(TPB);
    cfg.dynamicSmemBytes = 0;
    cfg.stream = 0;  // legacy default stream (same one <<<>>> targets)

    cudaLaunchAttribute attrs[1];
    attrs[0].id = cudaLaunchAttributeProgrammaticStreamSerialization;
    attrs[0].val.programmaticStreamSerializationAllowed = 1;
    cfg.attrs = attrs;
    cfg.numAttrs = 1;

    cudaLaunchKernelEx(&cfg, wsum_fused_kernel,
                       (const float4*)V0, (const float4*)V1,
                       (float4*)out, nv4_0, nv4_1);
}